// round 1
// baseline (speedup 1.0000x reference)
#include <cuda_runtime.h>
#include <math.h>

#define N_NODES 100000
#define S_DIST  4
#define NS      (N_NODES * S_DIST)     // 400000 samples
#define D       128
#define K       16
#define B       64
#define EPSI    0.2f
#define ITERS   100

// Scratch: row-max-normalized Gibbs kernel E_ij = exp((Mmin_i - M_ij)/eps), [NS, K]
__device__ float g_E[(size_t)NS * K];      // 25.6 MB, fits in L2
__device__ int   g_start[B + 1];

// ---------------------------------------------------------------------------
// Kernel 1: segment starts via binary search (batch_idx is sorted)
// ---------------------------------------------------------------------------
__global__ void starts_kernel(const int* __restrict__ bidx) {
    int b = threadIdx.x;           // 0..B (65 threads)
    if (b > B) return;
    int lo = 0, hi = N_NODES;      // first i with bidx[i] >= b  (b==B -> N)
    while (lo < hi) {
        int mid = (lo + hi) >> 1;
        if (bidx[mid] < b) lo = mid + 1; else hi = mid;
    }
    g_start[b] = lo;
}

// ---------------------------------------------------------------------------
// Kernel 2: E_ij = exp((Mmin_i - M_ij)/eps),  M = ||x||^2 + ||c||^2 - 2 x.c, clamped >= 0
// ---------------------------------------------------------------------------
__global__ void e_kernel(const float* __restrict__ X, const float* __restrict__ Cb) {
    __shared__ float4 sc[K * 32];     // codebook [16][128] as float4
    __shared__ float  scc[K];         // ||c_j||^2
    int tid = threadIdx.x;
    for (int i = tid; i < K * 32; i += blockDim.x)
        sc[i] = ((const float4*)Cb)[i];
    __syncthreads();
    if (tid < K) {
        float s = 0.f;
        for (int d = 0; d < 32; d++) {
            float4 c = sc[tid * 32 + d];
            s += c.x * c.x + c.y * c.y + c.z * c.z + c.w * c.w;
        }
        scc[tid] = s;
    }
    __syncthreads();

    for (int i = blockIdx.x * blockDim.x + tid; i < NS; i += gridDim.x * blockDim.x) {
        const float4* x4 = (const float4*)(X + (size_t)i * D);
        float acc[K];
        #pragma unroll
        for (int j = 0; j < K; j++) acc[j] = 0.f;
        float xx = 0.f;
        #pragma unroll 4
        for (int d = 0; d < 32; d++) {
            float4 xv = x4[d];
            xx += xv.x * xv.x + xv.y * xv.y + xv.z * xv.z + xv.w * xv.w;
            #pragma unroll
            for (int j = 0; j < K; j++) {
                float4 cv = sc[j * 32 + d];
                acc[j] += xv.x * cv.x + xv.y * cv.y + xv.z * cv.z + xv.w * cv.w;
            }
        }
        float M[K];
        float mmin = 3.4e38f;
        #pragma unroll
        for (int j = 0; j < K; j++) {
            float m = xx + scc[j] - 2.f * acc[j];
            m = fmaxf(m, 0.f);            // matches jnp.maximum(M, 0)
            M[j] = m;
            mmin = fminf(mmin, m);
        }
        float o[K];
        #pragma unroll
        for (int j = 0; j < K; j++)
            o[j] = __expf((mmin - M[j]) * (1.0f / EPSI));
        float4* e4 = (float4*)(g_E + (size_t)i * K);
        e4[0] = make_float4(o[0],  o[1],  o[2],  o[3]);
        e4[1] = make_float4(o[4],  o[5],  o[6],  o[7]);
        e4[2] = make_float4(o[8],  o[9],  o[10], o[11]);
        e4[3] = make_float4(o[12], o[13], o[14], o[15]);
    }
}

// ---------------------------------------------------------------------------
// Kernel 3: per-graph Sinkhorn, one CTA per segment, 100 iterations in-kernel.
//   p_ij = E_ij * G_j / den_i,  den_i = sum_j E_ij * G_j,  G_j = exp(g_j - max g)
//   S_j  = G_j * sum_i E_ij / den_i
//   g_j += log(n/K) - log(S_j + 1e-30)
// Output: marg_j = (1/K) * S_j/(S_j+1e-30) from final iteration; row-normalize.
// ---------------------------------------------------------------------------
__global__ __launch_bounds__(1024, 1) void sinkhorn_kernel(float* __restrict__ out) {
    __shared__ float sg[K], sG[K], sS[K], sM[K];
    __shared__ float wpart[32][K];     // per-warp partials

    int b   = blockIdx.x;
    int tid = threadIdx.x;
    int s0  = g_start[b]     * S_DIST;
    int s1  = g_start[b + 1] * S_DIST;
    int n   = s1 - s0;

    if (n <= 0) {                      // empty graph -> zero row
        if (tid < K) out[b * K + tid] = 0.f;
        return;
    }

    if (tid < K) sg[tid] = 0.f;
    float Cc  = logf((float)n) - logf((float)K);   // log_b - log_a
    int   wid = tid >> 5, lane = tid & 31;
    __syncthreads();

    for (int it = 0; it < ITERS; it++) {
        if (tid < K) {
            float gm = sg[0];
            #pragma unroll
            for (int j = 1; j < K; j++) gm = fmaxf(gm, sg[j]);
            sG[tid] = __expf(sg[tid] - gm);
        }
        __syncthreads();

        float acc[K];
        #pragma unroll
        for (int j = 0; j < K; j++) acc[j] = 0.f;

        for (int i = s0 + tid; i < s1; i += 1024) {
            const float4* e4 = (const float4*)(g_E + (size_t)i * K);
            float4 v0 = e4[0], v1 = e4[1], v2 = e4[2], v3 = e4[3];
            float e[K] = { v0.x, v0.y, v0.z, v0.w,  v1.x, v1.y, v1.z, v1.w,
                           v2.x, v2.y, v2.z, v2.w,  v3.x, v3.y, v3.z, v3.w };
            float den = 0.f;
            #pragma unroll
            for (int j = 0; j < K; j++) den += e[j] * sG[j];
            float r = __fdividef(1.0f, fmaxf(den, 1e-30f));
            #pragma unroll
            for (int j = 0; j < K; j++) acc[j] += e[j] * r;
        }

        // warp-level tree reduce of the 16 accumulators
        #pragma unroll
        for (int j = 0; j < K; j++) {
            #pragma unroll
            for (int o = 16; o > 0; o >>= 1)
                acc[j] += __shfl_xor_sync(0xffffffffu, acc[j], o);
        }
        if (lane == 0) {
            #pragma unroll
            for (int j = 0; j < K; j++) wpart[wid][j] = acc[j];
        }
        __syncthreads();

        if (tid < K) {
            float s = 0.f;
            #pragma unroll
            for (int w = 0; w < 32; w++) s += wpart[w][tid];
            float Sj = sG[tid] * s;
            sS[tid]  = Sj;                               // keep final-iter S
            sg[tid] += Cc - __logf(Sj + 1e-30f);
        }
        __syncthreads();
    }

    // marg_j = exp(log_b) * S_j/(S_j + 1e-30); then row-normalize with STAB_EPS
    if (tid < K) {
        float Sj = sS[tid];
        sM[tid]  = (1.0f / (float)K) * (Sj / (Sj + 1e-30f));
    }
    __syncthreads();
    if (tid < K) {
        float tot = 0.f;
        #pragma unroll
        for (int j = 0; j < K; j++) tot += sM[j];
        out[b * K + tid] = sM[tid] / fmaxf(tot, 1e-8f);
    }
}

// ---------------------------------------------------------------------------
extern "C" void kernel_launch(void* const* d_in, const int* in_sizes, int n_in,
                              void* d_out, int out_size) {
    const float* X    = (const float*)d_in[0];   // node_distributions [N,S,D] fp32
    const float* Cb   = (const float*)d_in[1];   // codebook [K,D] fp32
    const int*   bidx = (const int*)d_in[2];     // batch_idx [N] int32, sorted
    float*       out  = (float*)d_out;           // [B,K] fp32

    starts_kernel<<<1, B + 1>>>(bidx);
    int eblocks = (NS + 255) / 256;
    e_kernel<<<eblocks, 256>>>(X, Cb);
    sinkhorn_kernel<<<B, 1024>>>(out);
}

// round 2
// speedup vs baseline: 111.8272x; 111.8272x over previous
#include <cuda_runtime.h>

#define N_NODES 100000
#define K       16
#define B       64

// Reference semantics collapse analytically:
//   The scan body's LAST op is the g-update: g = log_b - seg_logsumexp(logK + f).
//   Hence the final plan's column marginal per segment is
//     marg_j = exp(g_j) * exp(seg_lse_j) = (1/K) * s/(s + 1e-30)  ==  1/K   (fp32-exact, s >= 1)
//   and after row-normalization: weights = 1/K for nonempty segments, 0 for empty.
//   (Round-1 full-Sinkhorn kernel provably emitted exactly 0.0625 and passed at
//    rel_err = 1.47e-5 — the reference's own fp32 noise floor.)
//
// So the kernel reduces to: find segment boundaries in sorted batch_idx, emit
// 1/16 for nonempty segments and 0 for empty ones.

__global__ void pool_kernel(const int* __restrict__ bidx, float* __restrict__ out) {
    __shared__ int sstart[B + 1];
    int tid = threadIdx.x;

    // 65 binary searches: sstart[b] = first i with bidx[i] >= b
    if (tid <= B) {
        int b = tid;
        int lo = 0, hi = N_NODES;
        while (lo < hi) {
            int mid = (lo + hi) >> 1;
            if (__ldg(&bidx[mid]) < b) lo = mid + 1; else hi = mid;
        }
        sstart[b] = lo;
    }
    __syncthreads();

    // B*K = 1024 outputs, one per thread
    int b = tid >> 4;                       // segment
    bool nonempty = sstart[b + 1] > sstart[b];
    out[tid] = nonempty ? (1.0f / (float)K) : 0.0f;
}

extern "C" void kernel_launch(void* const* d_in, const int* in_sizes, int n_in,
                              void* d_out, int out_size) {
    const int* bidx = (const int*)d_in[2];   // batch_idx [N] int32, sorted
    float*     out  = (float*)d_out;         // [B, K] fp32

    pool_kernel<<<1, B * K>>>(bidx, out);
}

// round 3
// speedup vs baseline: 146.2356x; 1.3077x over previous
#include <cuda_runtime.h>

#define N_NODES 100000
#define K       16
#define B       64
#define T       1024
#define STRIDE  ((N_NODES + T - 1) / T)   // 98

// Output is analytically (1/K) for nonempty segments, 0 for empty ones (the
// reference scan's final op projects column marginals to the uniform target
// exactly; confirmed bit-level in Rounds 1-2: rel_err pinned at 1.472e-5,
// the reference's own fp32 noise floor).
//
// Presence detection via breadth-first sampling of the sorted batch_idx:
//   Phase 1: 1024 parallel stride-98 samples mark their values present.
//   Phase 2: a value is only missable inside a gap whose endpoint samples
//            jump by >=2. Total value increase <= 63 => <= 31 such gaps,
//            <= 98 elements each (<= 3038 total, <= 3 independent loads per
//            thread). For uniform random data this phase does zero loads.

__global__ void pool_kernel(const int* __restrict__ bidx, float* __restrict__ out) {
    __shared__ int s[T];
    __shared__ int present[B];
    __shared__ int gbase[32], goff[32];
    __shared__ int gcount, gtotal;

    int tid = threadIdx.x;
    if (tid < B) present[tid] = 0;
    if (tid == 0) gcount = 0;

    // Phase 1: one fully-parallel sample round
    int idx = tid * STRIDE;
    if (idx > N_NODES - 1) idx = N_NODES - 1;
    int v = __ldg(&bidx[idx]);
    s[tid] = v;
    __syncthreads();

    present[v] = 1;                               // idempotent smem write

    // Gap detection: value jump >= 2 between consecutive samples
    if (tid < T - 1) {
        int v1 = s[tid + 1];
        if (v1 - v >= 2) {
            int base = idx + 1;
            int idx1 = (tid + 1) * STRIDE;
            if (idx1 > N_NODES - 1) idx1 = N_NODES - 1;
            int len = idx1 - base;                // elements strictly between
            if (len > 0) {
                int q = atomicAdd(&gcount, 1);
                gbase[q] = base;
                goff[q]  = len;                   // temporarily holds length
            }
        }
    }
    __syncthreads();

    int ng = gcount;
    if (ng > 0) {
        // serial prefix over <=31 entries
        if (tid == 0) {
            int acc = 0;
            for (int g = 0; g < ng; g++) {
                int len  = goff[g];
                goff[g]  = acc;                   // now exclusive offset
                acc     += len;
            }
            gtotal = acc;
        }
        __syncthreads();
        int W = gtotal;                           // <= 31 * 97 < 3 * T

        // Phase 2: <=3 independent loads per thread, hoisted before stores
        int w0 = -1, w1 = -1, w2 = -1;
        int i0 = tid, i1 = tid + T, i2 = tid + 2 * T;

        auto locate = [&](int item) -> int {
            // find gap g with goff[g] <= item, largest such g (linear, ng<=31)
            int g = 0;
            for (int x = 1; x < ng; x++) if (goff[x] <= item) g = x;
            return gbase[g] + (item - goff[g]);
        };
        if (i0 < W) w0 = __ldg(&bidx[locate(i0)]);
        if (i1 < W) w1 = __ldg(&bidx[locate(i1)]);
        if (i2 < W) w2 = __ldg(&bidx[locate(i2)]);
        if (w0 >= 0) present[w0] = 1;
        if (w1 >= 0) present[w1] = 1;
        if (w2 >= 0) present[w2] = 1;
    }
    __syncthreads();

    out[tid] = present[tid >> 4] ? (1.0f / (float)K) : 0.0f;
}

extern "C" void kernel_launch(void* const* d_in, const int* in_sizes, int n_in,
                              void* d_out, int out_size) {
    const int* bidx = (const int*)d_in[2];   // batch_idx [N] int32, sorted
    float*     out  = (float*)d_out;         // [B, K] fp32

    pool_kernel<<<1, T>>>(bidx, out);
}